// round 2
// baseline (speedup 1.0000x reference)
#include <cuda_runtime.h>
#include <math.h>

#define BB 64
#define SS 512
#define HH 1024
#define TT 24
#define NROWS (BB*SS)

// ---------------- device scratch (no allocations allowed) ----------------
__device__ float g_lse[NROWS];     // logsumexp_t emission[row,:]
__device__ float g_sc[NROWS];      // emission[row, target[row]]
__device__ float g_loss_sum;       // atomic accumulator (reset by last block)
__device__ unsigned g_ticket;      // completion counter (reset by last block)

__device__ __forceinline__ float neg_inf() { return __int_as_float(0xff800000); }

// packed 2-lane fp32 FMA (Blackwell): acc.lo += a.lo*b.lo ; acc.hi += a.hi*b.hi
#define FMA2(acc, a, b) \
    asm("fma.rn.f32x2 %0, %1, %2, %0;" : "+l"(acc) : "l"(a), "l"(b))

__device__ __forceinline__ float lo_f(unsigned long long v) { return __uint_as_float((unsigned)v); }
__device__ __forceinline__ float hi_f(unsigned long long v) { return __uint_as_float((unsigned)(v >> 32)); }

// ---------------- emission GEMM + fused LSE/score epilogue ----------------
// grid: 1024 blocks x 512 threads (16 warps). Warp computes 2 rows x 24 t.
// K split even/odd into f32x2 lanes -> packed FMA with zero packing MOVs.
// dyn smem: W as ulonglong2 [24][256] (98304B) + bias pad(128B) + sred [16][24] float2
#define SMEM_BYTES (98304 + 128 + 16*24*8)

__global__ void __launch_bounds__(512, 1)
emis_kernel(const float* __restrict__ feats,
            const float* __restrict__ W,
            const float* __restrict__ bias,
            const int*   __restrict__ target,
            float*       __restrict__ emis) {
    extern __shared__ unsigned char smem_raw[];
    ulonglong2* sW  = (ulonglong2*)smem_raw;                 // [24*256]
    float*      sb  = (float*)(smem_raw + 98304);            // [24]
    float2*     sred= (float2*)(smem_raw + 98304 + 128);     // [16][24]

    // stage W (row-major [T][H]) as 16B vectors, and bias
    {
        const ulonglong2* Wg = (const ulonglong2*)W;
        for (int i = threadIdx.x; i < TT * HH / 4; i += 512) sW[i] = Wg[i];
        if (threadIdx.x < TT) sb[threadIdx.x] = bias[threadIdx.x];
    }
    __syncthreads();

    const int warp = threadIdx.x >> 5;
    const int lane = threadIdx.x & 31;
    const long row0 = (long)blockIdx.x * 32 + warp * 2;
    const ulonglong2* f2 = (const ulonglong2*)feats;

    unsigned long long acc[TT][2];
    #pragma unroll
    for (int t = 0; t < TT; t++) { acc[t][0] = 0ULL; acc[t][1] = 0ULL; }

    #pragma unroll
    for (int it = 0; it < 8; it++) {
        const int k4 = it * 32 + lane;           // 16B-vector index in [0,256)
        ulonglong2 fa = f2[row0 * 256 + k4];
        ulonglong2 fb = f2[(row0 + 1) * 256 + k4];
        #pragma unroll
        for (int t = 0; t < TT; t++) {
            ulonglong2 w = sW[t * 256 + k4];
            FMA2(acc[t][0], fa.x, w.x);
            FMA2(acc[t][0], fa.y, w.y);
            FMA2(acc[t][1], fb.x, w.x);
            FMA2(acc[t][1], fb.y, w.y);
        }
    }

    // collapse f32x2 lanes, then warp-reduce each (t,row) partial to lane 0
    #pragma unroll
    for (int t = 0; t < TT; t++) {
        float va = lo_f(acc[t][0]) + hi_f(acc[t][0]);
        float vb = lo_f(acc[t][1]) + hi_f(acc[t][1]);
        va += __shfl_down_sync(0xffffffffu, va, 16);
        vb += __shfl_down_sync(0xffffffffu, vb, 16);
        va += __shfl_down_sync(0xffffffffu, va, 8);
        vb += __shfl_down_sync(0xffffffffu, vb, 8);
        va += __shfl_down_sync(0xffffffffu, va, 4);
        vb += __shfl_down_sync(0xffffffffu, vb, 4);
        va += __shfl_down_sync(0xffffffffu, va, 2);
        vb += __shfl_down_sync(0xffffffffu, vb, 2);
        va += __shfl_down_sync(0xffffffffu, va, 1);
        vb += __shfl_down_sync(0xffffffffu, vb, 1);
        if (lane == 0) sred[warp * TT + t] = make_float2(va, vb);
    }
    __syncwarp();

    float2 e2 = make_float2(0.0f, 0.0f);
    float  bval = 0.0f;
    if (lane < TT) { e2 = sred[warp * TT + lane]; bval = sb[lane]; }
    float er[2] = { e2.x + bval, e2.y + bval };

    #pragma unroll
    for (int r = 0; r < 2; r++) {
        const long row = row0 + r;
        float e = (lane < TT) ? er[r] : neg_inf();
        if (lane < TT) emis[row * TT + lane] = e;
        // logsumexp over t (lanes >= TT contribute -inf / 0)
        float m = e;
        m = fmaxf(m, __shfl_xor_sync(0xffffffffu, m, 16));
        m = fmaxf(m, __shfl_xor_sync(0xffffffffu, m, 8));
        m = fmaxf(m, __shfl_xor_sync(0xffffffffu, m, 4));
        m = fmaxf(m, __shfl_xor_sync(0xffffffffu, m, 2));
        m = fmaxf(m, __shfl_xor_sync(0xffffffffu, m, 1));
        float ex = (lane < TT) ? expf(e - m) : 0.0f;
        ex += __shfl_xor_sync(0xffffffffu, ex, 16);
        ex += __shfl_xor_sync(0xffffffffu, ex, 8);
        ex += __shfl_xor_sync(0xffffffffu, ex, 4);
        ex += __shfl_xor_sync(0xffffffffu, ex, 2);
        ex += __shfl_xor_sync(0xffffffffu, ex, 1);
        float lse = m + logf(ex);
        int tg = target[row];
        float sc = __shfl_sync(0xffffffffu, e, tg);
        if (lane == 0) { g_lse[row] = lse; g_sc[row] = sc; }
    }
}

// ---------------- fused tail: per-batch score/logZ + final loss ----------------
// grid: 64 blocks x 256 threads. Handles mask decode, transition-zero check,
// fast path, generic scan fallback, and ticket-based final loss write.
__global__ void batch_all_kernel(const float* __restrict__ trans,
                                 const int*   __restrict__ target,
                                 const float* __restrict__ emis,
                                 const void*  __restrict__ mask_raw,
                                 float*       __restrict__ out,
                                 int has_loss) {
    __shared__ float st[TT * TT];
    __shared__ float sp[TT];
    __shared__ float red[256];
    __shared__ int   s_nz;

    const int b = blockIdx.x;
    const int tid = threadIdx.x;

    if (tid == 0) s_nz = 0;
    __syncthreads();
    {
        int local = 0;
        for (int i = tid; i < TT * TT; i += 256) {
            float v = trans[i];
            st[i] = v;
            if (v != 0.0f) local = 1;
        }
        if (local) atomicOr(&s_nz, 1);
    }
    __syncthreads();
    const int nz = s_nz;

    // mask dtype auto-detect (mask[0][0..] is always true: lengths >= S/2)
    const unsigned u0 = *(const unsigned*)mask_raw;
    const int mt = (u0 == 0x01010101u) ? 0 : ((u0 == 0x3F800000u) ? 1 : 2);
    #define GET_MASK(idx) (mt == 0 ? (((const unsigned char*)mask_raw)[idx] != 0) \
                         : (mt == 1 ? (((const float*)mask_raw)[idx] != 0.0f)      \
                                    : (((const int*)mask_raw)[idx] != 0)))

    float val;
    if (!nz) {
        // fast path: logZ telescopes; total = sum_masked(sc) - (lse over masked + s==0)
        float sum = 0.0f;
        for (int s = tid; s < SS; s += 256) {
            const int idx = b * SS + s;
            const int m = GET_MASK(idx);
            float c = 0.0f;
            if (m) c += g_sc[idx];
            if (m || s == 0) c -= g_lse[idx];
            sum += c;
        }
        red[tid] = sum;
        __syncthreads();
        for (int off = 128; off > 0; off >>= 1) {
            if (tid < off) red[tid] += red[tid + off];
            __syncthreads();
        }
        val = red[0];
    } else {
        // generic path: full score with transitions + sequential scan (warp 0)
        float sum = 0.0f;
        for (int s = tid; s < SS; s += 256) {
            const long idx = (long)b * SS + s;
            if (GET_MASK(idx)) {
                float v = emis[idx * TT + target[idx]];
                if (s > 0) v += st[target[idx - 1] * TT + target[idx]];
                sum += v;
            }
        }
        red[tid] = sum;
        __syncthreads();
        for (int off = 128; off > 0; off >>= 1) {
            if (tid < off) red[tid] += red[tid + off];
            __syncthreads();
        }
        const float score = red[0];

        if (tid < 32) {
            const int lane = tid;
            if (lane < TT) sp[lane] = emis[(long)b * SS * TT + lane];
            __syncwarp();
            for (int s = 1; s < SS; s++) {
                if (GET_MASK(b * SS + s)) {
                    float nv = 0.0f;
                    if (lane < TT) {
                        float m = neg_inf();
                        #pragma unroll
                        for (int j = 0; j < TT; j++) m = fmaxf(m, sp[j] + st[j * TT + lane]);
                        float a = 0.0f;
                        #pragma unroll
                        for (int j = 0; j < TT; j++) a += expf(sp[j] + st[j * TT + lane] - m);
                        nv = emis[((long)b * SS + s) * TT + lane] + m + logf(a);
                    }
                    __syncwarp();
                    if (lane < TT) sp[lane] = nv;
                    __syncwarp();
                }
            }
            float e = (lane < TT) ? sp[lane] : neg_inf();
            float m = e;
            m = fmaxf(m, __shfl_xor_sync(0xffffffffu, m, 16));
            m = fmaxf(m, __shfl_xor_sync(0xffffffffu, m, 8));
            m = fmaxf(m, __shfl_xor_sync(0xffffffffu, m, 4));
            m = fmaxf(m, __shfl_xor_sync(0xffffffffu, m, 2));
            m = fmaxf(m, __shfl_xor_sync(0xffffffffu, m, 1));
            float ex = (lane < TT) ? expf(e - m) : 0.0f;
            ex += __shfl_xor_sync(0xffffffffu, ex, 16);
            ex += __shfl_xor_sync(0xffffffffu, ex, 8);
            ex += __shfl_xor_sync(0xffffffffu, ex, 4);
            ex += __shfl_xor_sync(0xffffffffu, ex, 2);
            ex += __shfl_xor_sync(0xffffffffu, ex, 1);
            if (lane == 0) red[0] = score - (m + logf(ex));
        }
        __syncthreads();
        val = red[0];
    }

    // ticket-based final loss (self-resetting for graph replay)
    if (tid == 0) {
        atomicAdd(&g_loss_sum, val);
        __threadfence();
        unsigned t = atomicAdd(&g_ticket, 1u);
        if (t == BB - 1) {
            if (has_loss) out[0] = -g_loss_sum / (float)BB;
            g_loss_sum = 0.0f;
            g_ticket = 0u;
        }
    }
}

// ---------------- launch ----------------
extern "C" void kernel_launch(void* const* d_in, const int* in_sizes, int n_in,
                              void* d_out, int out_size) {
    const float* feats  = (const float*)d_in[0];   // (B,S,H)
    const int*   target = (const int*)d_in[1];     // (B,S)
    const void*  mask   = d_in[2];                 // (B,S) dtype auto-detected
    const float* W      = (const float*)d_in[3];   // (T,H)
    const float* bias   = (const float*)d_in[4];   // (T,)
    const float* trans  = (const float*)d_in[5];   // (T,T)

    float* out = (float*)d_out;
    const int has_loss = (out_size == NROWS * TT + 1) ? 1 : 0;
    float* emis = out + has_loss;                  // (loss, emission) flattened

    static int attr_set = 0;
    if (!attr_set) {
        cudaFuncSetAttribute(emis_kernel, cudaFuncAttributeMaxDynamicSharedMemorySize, SMEM_BYTES);
        attr_set = 1;
    }

    emis_kernel<<<NROWS / 32, 512, SMEM_BYTES>>>(feats, W, bias, target, emis);
    batch_all_kernel<<<BB, 256>>>(trans, target, emis, mask, out, has_loss);
}

// round 3
// speedup vs baseline: 1.4610x; 1.4610x over previous
#include <cuda_runtime.h>
#include <math.h>

#define BB 64
#define SS 512
#define HH 1024
#define TT 24
#define NROWS (BB*SS)

#define ROWS_PER_BLK 128
#define NBLK (NROWS/ROWS_PER_BLK)        // 256 blocks
#define NCHUNK (HH/32)                   // 32 k-chunks of 32 floats
#define NSTAGE 4
#define TILE_F4_STRIDE 9                 // 8 float4 data + 1 pad (anti-conflict)
#define TILE_BYTES (ROWS_PER_BLK*TILE_F4_STRIDE*16)   // 18432
#define W_F4_STRIDE 257                  // 256 float4 data + 1 pad
#define W_BYTES (TT*W_F4_STRIDE*16)      // 98688
#define SMEM_TOTAL (W_BYTES + NSTAGE*TILE_BYTES + 256) // + bias + reduce

// ---------------- device scratch ----------------
__device__ float    g_loss_sum;
__device__ unsigned g_ticket;

__device__ __forceinline__ float neg_inf() { return __int_as_float(0xff800000); }

#define FMA2(acc, a, b) \
    asm("fma.rn.f32x2 %0, %1, %2, %0;" : "+l"(acc) : "l"(a), "l"(b))
__device__ __forceinline__ float lo_f(unsigned long long v) { return __uint_as_float((unsigned)v); }
__device__ __forceinline__ float hi_f(unsigned long long v) { return __uint_as_float((unsigned)(v >> 32)); }

__device__ __forceinline__ void cp_async16(unsigned s, const void* g) {
    asm volatile("cp.async.cg.shared.global [%0], [%1], 16;" :: "r"(s), "l"(g));
}
#define CP_COMMIT() asm volatile("cp.async.commit_group;")
#define CP_WAIT2()  asm volatile("cp.async.wait_group 2;")

__device__ __forceinline__ int getmask(const void* p, int mt, long i) {
    return mt == 0 ? (((const unsigned char*)p)[i] != 0)
         : mt == 1 ? (((const float*)p)[i] != 0.0f)
                   : (((const int*)p)[i] != 0);
}

// ================= single fused kernel =================
__global__ void __launch_bounds__(256, 1)
crf_kernel(const float* __restrict__ feats, const float* __restrict__ W,
           const float* __restrict__ bias, const int* __restrict__ target,
           const void* __restrict__ mask_raw, const float* __restrict__ trans,
           float* __restrict__ out, int has_loss) {
    extern __shared__ unsigned char smem[];
    ulonglong2*    sW       = (ulonglong2*)smem;                  // [24][257] f4
    unsigned char* tileBase = smem + W_BYTES;                     // 4 stages
    float*         sb       = (float*)(smem + W_BYTES + NSTAGE*TILE_BYTES);
    float*         sred     = sb + 32;                            // 8 warp partials
    __shared__ int   s_flag, s_nz;
    __shared__ float s_tot;

    const int  tid = threadIdx.x;
    const long blkrow0 = (long)blockIdx.x * ROWS_PER_BLK;
    const float4* f4g = (const float4*)feats;

    // --- prologue: async-stage chunks 0..2 ---
    #pragma unroll
    for (int c = 0; c < NSTAGE - 1; c++) {
        unsigned sb32 = (unsigned)__cvta_generic_to_shared(tileBase + c * TILE_BYTES);
        #pragma unroll
        for (int j = 0; j < 4; j++) {
            int u = tid + j * 256;
            int r = u >> 3, cc = u & 7;
            cp_async16(sb32 + (unsigned)(r * TILE_F4_STRIDE + cc) * 16,
                       f4g + ((blkrow0 + r) * 256 + c * 8 + cc));
        }
        CP_COMMIT();
    }
    // stage W (padded rows) + bias, overlapped with the async loads
    for (int i = tid; i < TT * 256; i += 256) {
        int t = i >> 8, c = i & 255;
        ((float4*)sW)[t * W_F4_STRIDE + c] = ((const float4*)W)[i];
    }
    if (tid < TT) sb[tid] = bias[tid];
    __syncthreads();

    const int warp = tid >> 5, lane = tid & 31;
    const int rg = lane >> 3, cg = lane & 7;
    const int rowl0 = warp * 16 + rg;       // thread rows: rowl0 + rr*4
    const int t0 = cg * 3;
    const ulonglong2* wp = sW + t0 * W_F4_STRIDE;

    unsigned long long acc[4][3];
    #pragma unroll
    for (int r = 0; r < 4; r++)
        #pragma unroll
        for (int c = 0; c < 3; c++) acc[r][c] = 0ULL;

    // --- main loop: 32 chunks of 32 k ---
    for (int ch = 0; ch < NCHUNK; ch++) {
        CP_WAIT2();
        __syncthreads();
        const ulonglong2* tf = (const ulonglong2*)(tileBase + (ch & 3) * TILE_BYTES);
        const int kb = ch * 8;
        #pragma unroll
        for (int c4 = 0; c4 < 8; c4++) {
            ulonglong2 w0 = wp[0 * W_F4_STRIDE + kb + c4];
            ulonglong2 w1 = wp[1 * W_F4_STRIDE + kb + c4];
            ulonglong2 w2 = wp[2 * W_F4_STRIDE + kb + c4];
            ulonglong2 f0 = tf[(rowl0 +  0) * TILE_F4_STRIDE + c4];
            ulonglong2 f1 = tf[(rowl0 +  4) * TILE_F4_STRIDE + c4];
            ulonglong2 f2 = tf[(rowl0 +  8) * TILE_F4_STRIDE + c4];
            ulonglong2 f3 = tf[(rowl0 + 12) * TILE_F4_STRIDE + c4];
            FMA2(acc[0][0], f0.x, w0.x); FMA2(acc[0][0], f0.y, w0.y);
            FMA2(acc[0][1], f0.x, w1.x); FMA2(acc[0][1], f0.y, w1.y);
            FMA2(acc[0][2], f0.x, w2.x); FMA2(acc[0][2], f0.y, w2.y);
            FMA2(acc[1][0], f1.x, w0.x); FMA2(acc[1][0], f1.y, w0.y);
            FMA2(acc[1][1], f1.x, w1.x); FMA2(acc[1][1], f1.y, w1.y);
            FMA2(acc[1][2], f1.x, w2.x); FMA2(acc[1][2], f1.y, w2.y);
            FMA2(acc[2][0], f2.x, w0.x); FMA2(acc[2][0], f2.y, w0.y);
            FMA2(acc[2][1], f2.x, w1.x); FMA2(acc[2][1], f2.y, w1.y);
            FMA2(acc[2][2], f2.x, w2.x); FMA2(acc[2][2], f2.y, w2.y);
            FMA2(acc[3][0], f3.x, w0.x); FMA2(acc[3][0], f3.y, w0.y);
            FMA2(acc[3][1], f3.x, w1.x); FMA2(acc[3][1], f3.y, w1.y);
            FMA2(acc[3][2], f3.x, w2.x); FMA2(acc[3][2], f3.y, w2.y);
        }
        const int nc = ch + 3;
        if (nc < NCHUNK) {
            unsigned sb32 = (unsigned)__cvta_generic_to_shared(tileBase + (nc & 3) * TILE_BYTES);
            #pragma unroll
            for (int j = 0; j < 4; j++) {
                int u = tid + j * 256;
                int r = u >> 3, cc = u & 7;
                cp_async16(sb32 + (unsigned)(r * TILE_F4_STRIDE + cc) * 16,
                           f4g + ((blkrow0 + r) * 256 + nc * 8 + cc));
            }
        }
        CP_COMMIT();   // one group per iter keeps wait_group bookkeeping uniform
    }

    // --- epilogue: bias, store emission, octet LSE + target score, fast-path loss ---
    float* emis = out + has_loss;
    const unsigned u0 = *(const unsigned*)mask_raw;
    const int mt = (u0 == 0x01010101u) ? 0 : ((u0 == 0x3F800000u) ? 1 : 2);
    const float b0 = sb[t0], b1 = sb[t0 + 1], b2 = sb[t0 + 2];

    float contrib = 0.0f;
    #pragma unroll
    for (int rr = 0; rr < 4; rr++) {
        const long row = blkrow0 + rowl0 + rr * 4;
        float e0 = lo_f(acc[rr][0]) + hi_f(acc[rr][0]) + b0;
        float e1 = lo_f(acc[rr][1]) + hi_f(acc[rr][1]) + b1;
        float e2 = lo_f(acc[rr][2]) + hi_f(acc[rr][2]) + b2;
        emis[row * TT + t0 + 0] = e0;
        emis[row * TT + t0 + 1] = e1;
        emis[row * TT + t0 + 2] = e2;
        // max over full row (octet = 8 lanes x 3 t)
        float m = fmaxf(e0, fmaxf(e1, e2));
        m = fmaxf(m, __shfl_xor_sync(0xffffffffu, m, 1));
        m = fmaxf(m, __shfl_xor_sync(0xffffffffu, m, 2));
        m = fmaxf(m, __shfl_xor_sync(0xffffffffu, m, 4));
        float ex = expf(e0 - m) + expf(e1 - m) + expf(e2 - m);
        const int tg = target[row];
        float sc = (tg == t0 ? e0 : 0.0f) + (tg == t0 + 1 ? e1 : 0.0f) + (tg == t0 + 2 ? e2 : 0.0f);
        ex += __shfl_xor_sync(0xffffffffu, ex, 1);
        sc += __shfl_xor_sync(0xffffffffu, sc, 1);
        ex += __shfl_xor_sync(0xffffffffu, ex, 2);
        sc += __shfl_xor_sync(0xffffffffu, sc, 2);
        ex += __shfl_xor_sync(0xffffffffu, ex, 4);
        sc += __shfl_xor_sync(0xffffffffu, sc, 4);
        if (cg == 0) {
            const float lse = m + logf(ex);
            const int s = (int)(row & (SS - 1));
            const int mk = getmask(mask_raw, mt, row);
            contrib += mk ? (sc - lse) : (s == 0 ? -lse : 0.0f);
        }
    }
    // warp + block reduce the fast-path contribution
    contrib += __shfl_xor_sync(0xffffffffu, contrib, 16);
    contrib += __shfl_xor_sync(0xffffffffu, contrib, 8);
    contrib += __shfl_xor_sync(0xffffffffu, contrib, 4);
    contrib += __shfl_xor_sync(0xffffffffu, contrib, 2);
    contrib += __shfl_xor_sync(0xffffffffu, contrib, 1);
    if (lane == 0) sred[warp] = contrib;
    __syncthreads();
    if (tid == 0) {
        float part = 0.0f;
        #pragma unroll
        for (int w = 0; w < 8; w++) part += sred[w];
        atomicAdd(&g_loss_sum, part);
        __threadfence();
        unsigned tk = atomicAdd(&g_ticket, 1u);
        s_flag = (tk == NBLK - 1);
        s_nz = 0;
        s_tot = 0.0f;
    }
    __syncthreads();
    if (!s_flag) return;

    // ================= last block: finalize loss =================
    float* st = (float*)tileBase;         // transition [576], tiles no longer needed
    float* sp = st + 576;                 // per-warp scan state [8][24]
    {
        int lnz = 0;
        for (int i = tid; i < TT * TT; i += 256) {
            float v = trans[i];
            st[i] = v;
            lnz |= (v != 0.0f);
        }
        if (lnz) atomicOr(&s_nz, 1);
    }
    __syncthreads();

    if (!s_nz) {
        if (tid == 0) {
            if (has_loss) out[0] = -g_loss_sum / (float)BB;
            g_loss_sum = 0.0f;
            g_ticket = 0u;
        }
        return;
    }

    // generic transition path (not taken for this dataset): warp per batch group
    {
        const unsigned um0 = *(const unsigned*)mask_raw;
        const int mtt = (um0 == 0x01010101u) ? 0 : ((um0 == 0x3F800000u) ? 1 : 2);
        float wsum = 0.0f;
        float* msp = sp + warp * TT;
        for (int b = warp; b < BB; b += 8) {
            float sum = 0.0f;
            for (int s = lane; s < SS; s += 32) {
                const long idx = (long)b * SS + s;
                if (getmask(mask_raw, mtt, idx)) {
                    float v = emis[idx * TT + target[idx]];
                    if (s > 0) v += st[target[idx - 1] * TT + target[idx]];
                    sum += v;
                }
            }
            sum += __shfl_xor_sync(0xffffffffu, sum, 16);
            sum += __shfl_xor_sync(0xffffffffu, sum, 8);
            sum += __shfl_xor_sync(0xffffffffu, sum, 4);
            sum += __shfl_xor_sync(0xffffffffu, sum, 2);
            sum += __shfl_xor_sync(0xffffffffu, sum, 1);

            if (lane < TT) msp[lane] = emis[(long)b * SS * TT + lane];
            __syncwarp();
            for (int s = 1; s < SS; s++) {
                if (getmask(mask_raw, mtt, (long)b * SS + s)) {
                    float nv = 0.0f;
                    if (lane < TT) {
                        float m = neg_inf();
                        #pragma unroll
                        for (int j = 0; j < TT; j++) m = fmaxf(m, msp[j] + st[j * TT + lane]);
                        float a = 0.0f;
                        #pragma unroll
                        for (int j = 0; j < TT; j++) a += expf(msp[j] + st[j * TT + lane] - m);
                        nv = emis[((long)b * SS + s) * TT + lane] + m + logf(a);
                    }
                    __syncwarp();
                    if (lane < TT) msp[lane] = nv;
                    __syncwarp();
                }
            }
            float e = (lane < TT) ? msp[lane] : neg_inf();
            float m = e;
            m = fmaxf(m, __shfl_xor_sync(0xffffffffu, m, 16));
            m = fmaxf(m, __shfl_xor_sync(0xffffffffu, m, 8));
            m = fmaxf(m, __shfl_xor_sync(0xffffffffu, m, 4));
            m = fmaxf(m, __shfl_xor_sync(0xffffffffu, m, 2));
            m = fmaxf(m, __shfl_xor_sync(0xffffffffu, m, 1));
            float ex2 = (lane < TT) ? expf(e - m) : 0.0f;
            ex2 += __shfl_xor_sync(0xffffffffu, ex2, 16);
            ex2 += __shfl_xor_sync(0xffffffffu, ex2, 8);
            ex2 += __shfl_xor_sync(0xffffffffu, ex2, 4);
            ex2 += __shfl_xor_sync(0xffffffffu, ex2, 2);
            ex2 += __shfl_xor_sync(0xffffffffu, ex2, 1);
            if (lane == 0) wsum += sum - (m + logf(ex2));
        }
        if (lane == 0) atomicAdd(&s_tot, wsum);
    }
    __syncthreads();
    if (tid == 0) {
        if (has_loss) out[0] = -s_tot / (float)BB;
        g_loss_sum = 0.0f;
        g_ticket = 0u;
    }
}

// ---------------- launch ----------------
extern "C" void kernel_launch(void* const* d_in, const int* in_sizes, int n_in,
                              void* d_out, int out_size) {
    const float* feats  = (const float*)d_in[0];   // (B,S,H)
    const int*   target = (const int*)d_in[1];     // (B,S)
    const void*  mask   = d_in[2];                 // (B,S) dtype auto-detected
    const float* W      = (const float*)d_in[3];   // (T,H)
    const float* bias   = (const float*)d_in[4];   // (T,)
    const float* trans  = (const float*)d_in[5];   // (T,T)

    float* out = (float*)d_out;
    const int has_loss = (out_size == NROWS * TT + 1) ? 1 : 0;

    static int attr_set = 0;
    if (!attr_set) {
        cudaFuncSetAttribute(crf_kernel, cudaFuncAttributeMaxDynamicSharedMemorySize, SMEM_TOTAL);
        attr_set = 1;
    }

    crf_kernel<<<NBLK, 256, SMEM_TOTAL>>>(feats, W, bias, target, mask, trans, out, has_loss);
}